// round 15
// baseline (speedup 1.0000x reference)
#include <cuda_runtime.h>
#include <cuda_bf16.h>
#include <cstdint>
#include <cmath>

// Problem constants (fixed by reference)
#define NROW 8192       // N
#define NCLS 8192       // NB_CLASSES
#define DIM  128        // SZ_EMBED

__device__ __forceinline__ float flog2(float x){ float y; asm("lg2.approx.f32 %0, %1;" : "=f"(y) : "f"(x)); return y; }
__device__ __forceinline__ float fexp2(float x){ float y; asm("ex2.approx.f32 %0, %1;" : "=f"(y) : "f"(x)); return y; }
__device__ __forceinline__ float frcp (float x){ float y; asm("rcp.approx.f32 %0, %1;" : "=f"(y) : "f"(x)); return y; }
__device__ __forceinline__ float fsqrt(float x){ float y; asm("sqrt.approx.f32 %0, %1;" : "=f"(y) : "f"(x)); return y; }
__device__ __forceinline__ uint32_t f2tf32(float x){ uint32_t y; asm("cvt.rna.tf32.f32 %0, %1;" : "=r"(y) : "f"(x)); return y; }

#define CP_ASYNC16(dst32, srcp) \
    asm volatile("cp.async.cg.shared.global [%0], [%1], 16;" :: "r"(dst32), "l"(srcp))
#define CP_COMMIT()  asm volatile("cp.async.commit_group;")
#define CP_WAIT0()   asm volatile("cp.async.wait_group 0;")

__constant__ float c_C        = 0.1f;
__constant__ float c_SQRTC    = 0.31622776601683794f;
__constant__ float c_INVSQRTC = 3.1622776601683795f;   // 1/sqrt(c) = sqrt(10)

// K-permutation for LDS.64 fragment loads: within each 16-col tile and 8-col
// half, original col c (0..7) -> 2*(c&3) + (c>>2). Pairs (t4, t4+4) land on
// adjacent floats. Dot products are invariant under shared K-permutation.
__device__ __forceinline__ int kperm(int k) {
    int tt = k >> 4, w = k & 15, ks = w >> 3, c = w & 7;
    return (tt << 4) + (ks << 3) + ((c & 3) << 1) + (c >> 2);
}

// Scratch (static device allocations are allowed)
__device__ float  g_P [NCLS * DIM];  // projected proxies (tf32-rounded, natural order)
__device__ float  g_Pt[NCLS * DIM];  // projected proxies (tf32-rounded, K-permuted)
__device__ float  g_Xt[NROW * DIM];  // X (tf32-rounded, K-permuted)
__device__ float  g_y2[NCLS];        // ||P_j||^2
__device__ float  g_x2[NROW];        // ||X_i||^2
__device__ double g_acc[3];          // 0: neg_sum, 1: pos_sum, 2: neg_corr
__device__ int    g_flags[NCLS];
__device__ int    g_numvalid;

// ---------------------------------------------------------------------------
// prep: bid < NCLS -> project proxy row; else -> x2 + tf32 K-permuted copy of X.
__global__ void prep_kernel(const float* __restrict__ Ptan,
                            const float* __restrict__ X) {
    int bid = blockIdx.x;
    int t = threadIdx.x;
    __shared__ float ws[4];

    if (bid < NCLS) {
        int row = bid;
        float p = Ptan[row * DIM + t];
        float s = p * p;
        #pragma unroll
        for (int off = 16; off > 0; off >>= 1) s += __shfl_xor_sync(0xffffffffu, s, off);
        if ((t & 31) == 0) ws[t >> 5] = s;
        __syncthreads();
        float sum = ws[0] + ws[1] + ws[2] + ws[3];

        float nrm = fmaxf(sqrtf(sum), 1e-15f);
        float sc1 = fminf(1.0f, 2.3f / nrm);        // feature clipping
        p *= sc1;
        float un = fmaxf(nrm * sc1, 1e-15f);
        float a  = c_SQRTC * un;
        float th = tanhf(a);
        float g  = th * p / a;                       // expmap0
        float gn = fmaxf(th * c_INVSQRTC, 1e-15f);   // ||g|| = tanh(a)/sqrt(c)
        const float maxnorm = (1.0f - 1e-3f) * 3.1622776601683795f;
        float sc2 = (gn > maxnorm) ? (maxnorm / gn) : 1.0f;
        g *= sc2;
        float gt = __uint_as_float(f2tf32(g));
        g_P [row * DIM + t]        = gt;             // natural (for pos_kernel)
        g_Pt[row * DIM + kperm(t)] = gt;             // permuted (for GEMM)
        if (t == 0) {
            float gf = fminf(gn, maxnorm);
            g_y2[row] = gf * gf;
        }
    } else {
        int row = bid - NCLS;
        float v = X[row * DIM + t];
        g_Xt[row * DIM + kperm(t)] = __uint_as_float(f2tf32(v));
        float s = v * v;
        #pragma unroll
        for (int off = 16; off > 0; off >>= 1) s += __shfl_xor_sync(0xffffffffu, s, off);
        if ((t & 31) == 0) ws[t >> 5] = s;
        __syncthreads();
        if (t == 0) g_x2[row] = ws[0] + ws[1] + ws[2] + ws[3];
    }
}

// ---------------------------------------------------------------------------
// scatter flags + zero accumulators (flags were cleared by count_kernel of the
// previous replay; __device__ globals are zero-initialized on first load).
__global__ void scatter_kernel(const int* __restrict__ T) {
    int i = blockIdx.x * blockDim.x + threadIdx.x;
    if (i < NROW) g_flags[T[i]] = 1;
    if (blockIdx.x == 0 && threadIdx.x < 3) g_acc[threadIdx.x] = 0.0;
}

// count valid classes, then self-clear flags for the next graph replay.
__global__ void count_kernel() {
    int t = threadIdx.x;
    int s = 0;
    for (int i = t; i < NCLS; i += 1024) { s += g_flags[i]; g_flags[i] = 0; }
    #pragma unroll
    for (int off = 16; off > 0; off >>= 1) s += __shfl_xor_sync(0xffffffffu, s, off);
    __shared__ int ws[32];
    if ((t & 31) == 0) ws[t >> 5] = s;
    __syncthreads();
    if (t < 32) {
        int v = ws[t];
        #pragma unroll
        for (int off = 16; off > 0; off >>= 1) v += __shfl_xor_sync(0xffffffffu, v, off);
        if (t == 0) g_numvalid = v;
    }
}

// ---------------------------------------------------------------------------
// Positive pairs (round-11 proven config): 64 blocks x 256, each warp handles
// 16 pairs serially; full-precision dot + distance; warp-total double atomics.
__global__ void pos_kernel(const float* __restrict__ X, const int* __restrict__ T) {
    const int wid  = threadIdx.x >> 5;
    const int lane = threadIdx.x & 31;
    const int base = blockIdx.x * 128 + wid * 16;

    float poss = 0.0f, negc = 0.0f;
    for (int k = 0; k < 16; k++) {
        const int i = base + k;
        const int j = __ldg(&T[i]);
        const float* xr = &X  [i * DIM];
        const float* pr = &g_P[j * DIM];
        float dot = 0.0f;
        #pragma unroll
        for (int u = 0; u < 4; u++)
            dot = fmaf(xr[lane + u * 32], pr[lane + u * 32], dot);
        #pragma unroll
        for (int off = 16; off > 0; off >>= 1)
            dot += __shfl_xor_sync(0xffffffffu, dot, off);
        if (lane == 0) {
            const float C  = 0.1f;
            const float x2 = g_x2[i];
            const float y2 = g_y2[j];
            float t2 = fmaxf(x2 - 2.0f * dot + y2, 0.0f);     // ||x-y||^2
            float u  = 2.0f * C * t2 / ((1.0f - C * x2) * (1.0f - C * y2));
            float w  = 1.0f + u + sqrtf(u * (u + 2.0f));
            float d  = 3.1622776601683795f * logf(w);          // (1/sqrt(c))*arcosh(1+u)
            float sn = log1pf(expf(-d));                       // softplus(-d)
            poss += d + sn;                                    // softplus(d)
            negc += sn;
        }
    }
    if (lane == 0) {
        atomicAdd(&g_acc[1], (double)poss);
        atomicAdd(&g_acc[2], (double)negc);
    }
}

// ---------------------------------------------------------------------------
// Fused tf32 tensor-core GEMM (xy = X @ P^T) + Poincare distance + softplus(-d)
// over ALL pairs (positives corrected by pos_kernel).
// BM=BN=128, BK=16. 256 threads = 8 warps (4 in M x 2 in N), warp tile 32x64.
// K-permuted operands -> every fragment load is one LDS.64 (halves LDS count).
// SSTR=20 (proven store banking): float2 addrs g*20+2*t4 are 8B-aligned and
// conflict-free in every 8-lane phase. Smem = 40KB + scalar.
#define SSTR 20

__device__ __forceinline__ void mma_tf32_v(float* d, uint32_t a0, uint32_t a1,
                                           uint32_t a2, uint32_t a3,
                                           uint32_t b0, uint32_t b1) {
    asm volatile(
        "mma.sync.aligned.m16n8k8.row.col.f32.tf32.tf32.f32 "
        "{%0,%1,%2,%3}, {%4,%5,%6,%7}, {%8,%9}, {%0,%1,%2,%3};"
        : "+f"(d[0]), "+f"(d[1]), "+f"(d[2]), "+f"(d[3])
        : "r"(a0), "r"(a1), "r"(a2), "r"(a3), "r"(b0), "r"(b1));
}

__global__ __launch_bounds__(256, 2)
void fused_kernel() {
    __shared__ __align__(16) float Xs[2][128][SSTR];
    __shared__ __align__(16) float Ps[2][128][SSTR];
    __shared__ float sred;

    const int tid  = threadIdx.x;
    const int wid  = tid >> 5;
    const int lane = tid & 31;
    const int wm   = wid & 3;        // warp row 0..3 (M)
    const int wn   = wid >> 2;       // warp col 0..1 (N)
    const int g    = lane >> 2;      // group id 0..7
    const int t4   = lane & 3;       // thread in group 0..3
    const int rowBase = blockIdx.y * 128;
    const int colBase = blockIdx.x * 128;

    // staging map: each thread copies 2 x 16B of X and 2 x 16B of P per tile
    const int lrow = tid >> 1;          // 0..127
    const int lc0  = (tid & 1) * 2;     // float4 index base {0,2}
    const float* xg = &g_Xt[(rowBase + lrow) * DIM];
    const float* pg = &g_Pt[(colBase + lrow) * DIM];

    uint32_t xs_dst[2], ps_dst[2];
    #pragma unroll
    for (int u = 0; u < 2; u++) {
        xs_dst[u] = (uint32_t)__cvta_generic_to_shared(&Xs[0][lrow][(lc0 + u) * 4]);
        ps_dst[u] = (uint32_t)__cvta_generic_to_shared(&Ps[0][lrow][(lc0 + u) * 4]);
    }
    const uint32_t bufStride = (uint32_t)((char*)&Xs[1][0][0] - (char*)&Xs[0][0][0]);

    float acc[2][8][4];
    #pragma unroll
    for (int mt = 0; mt < 2; mt++)
        #pragma unroll
        for (int nt = 0; nt < 8; nt++)
            #pragma unroll
            for (int c = 0; c < 4; c++) acc[mt][nt][c] = 0.0f;

    // prefetch tile 0 into buffer 0
    #pragma unroll
    for (int u = 0; u < 2; u++) {
        CP_ASYNC16(xs_dst[u], xg + (lc0 + u) * 4);
        CP_ASYNC16(ps_dst[u], pg + (lc0 + u) * 4);
    }
    CP_COMMIT();

    const int rA = wm * 32;     // warp M offset in tile
    const int nB = wn * 64;     // warp N offset in tile

    int buf = 0;
    #pragma unroll
    for (int tt = 0; tt < DIM / 16; tt++) {
        CP_WAIT0();
        __syncthreads();
        // prefetch next tile into the other buffer (overlaps compute below)
        if (tt < DIM / 16 - 1) {
            const int kn = (tt + 1) * 16;
            const uint32_t off = (buf ^ 1) ? bufStride : 0u;
            #pragma unroll
            for (int u = 0; u < 2; u++) {
                CP_ASYNC16(xs_dst[u] + off, xg + kn + (lc0 + u) * 4);
                CP_ASYNC16(ps_dst[u] + off, pg + kn + (lc0 + u) * 4);
            }
            CP_COMMIT();
        }
        // compute current tile: 2 k8 steps. Permuted layout: fragment pair
        // (orig k+t4, k+t4+4) sits at floats [k8+2*t4, k8+2*t4+1] -> LDS.64.
        #pragma unroll
        for (int ks = 0; ks < 2; ks++) {
            const int kc = ks * 8 + 2 * t4;
            float2 bf[8];
            #pragma unroll
            for (int nt = 0; nt < 8; nt++)
                bf[nt] = *(const float2*)&Ps[buf][nB + nt * 8 + g][kc];
            #pragma unroll
            for (int mt = 0; mt < 2; mt++) {
                const float2 a02 = *(const float2*)&Xs[buf][rA + mt * 16 + g][kc];
                const float2 a13 = *(const float2*)&Xs[buf][rA + mt * 16 + g + 8][kc];
                const uint32_t a0 = __float_as_uint(a02.x);
                const uint32_t a1 = __float_as_uint(a13.x);
                const uint32_t a2 = __float_as_uint(a02.y);
                const uint32_t a3 = __float_as_uint(a13.y);
                #pragma unroll
                for (int nt = 0; nt < 8; nt++)
                    mma_tf32_v(acc[mt][nt], a0, a1, a2, a3,
                               __float_as_uint(bf[nt].x), __float_as_uint(bf[nt].y));
            }
        }
        __syncthreads();   // all reads of buf done before it is overwritten next iter
        buf ^= 1;
    }

    // ---------------- Epilogue (negatives only, arcosh form) ----------------
    // element (mt, nt, c): row h = mt*2 + (c>>1), col q = nt*2 + (c&1)
    const int rowW = rowBase + rA;
    const int colW = colBase + nB;
    const float C = c_C;

    float x2r[4], bx2c[4];
    #pragma unroll
    for (int h = 0; h < 4; h++) {
        int r = rowW + (h >> 1) * 16 + (h & 1) * 8 + g;
        float x2 = __ldg(&g_x2[r]);
        x2r[h]  = x2;
        bx2c[h] = 2.0f * C * frcp(1.0f - C * x2);    // 2c/(1-c*x2)
    }
    float y2c[16], byc[16];
    #pragma unroll
    for (int q = 0; q < 16; q++) {
        int cc = colW + (q >> 1) * 8 + 2 * t4 + (q & 1);
        float y2 = __ldg(&g_y2[cc]);
        y2c[q] = y2;
        byc[q] = frcp(1.0f - C * y2);                // 1/(1-c*y2)
    }

    const float KNEG = -3.1622776601683795f;         // -1/sqrt(c)
    float negs = 0.0f;

    #pragma unroll
    for (int mt = 0; mt < 2; mt++) {
        #pragma unroll
        for (int nt = 0; nt < 8; nt++) {
            #pragma unroll
            for (int c = 0; c < 4; c++) {
                const int h = mt * 2 + (c >> 1);
                const int q = nt * 2 + (c & 1);
                const float xy = acc[mt][nt][c];
                float t = fmaf(-2.0f, xy, x2r[h]);   // ||x-y||^2 = x2 - 2xy + y2
                t += y2c[q];
                t = fmaxf(t, 0.0f);
                float u = t * bx2c[h] * byc[q];      // 2c||x-y||^2/((1-cx2)(1-cy2))
                float v = u + 2.0f;
                float s = fsqrt(u * v);              // sqrt(u^2+2u)
                float w = (1.0f + u) + s;            // arcosh(1+u) = ln(w)
                float L = flog2(w);
                float e = fexp2(KNEG * L);           // exp(-d), d = ln(w)/sqrt(c)
                negs = fmaf(0.6931471805599453f, flog2(1.0f + e), negs);  // +softplus(-d)
            }
        }
    }

    // block reduction -> double atomic
    #pragma unroll
    for (int off = 16; off > 0; off >>= 1)
        negs += __shfl_xor_sync(0xffffffffu, negs, off);
    if (tid == 0) sred = 0.0f;
    __syncthreads();
    if (lane == 0) atomicAdd(&sred, negs);
    __syncthreads();
    if (tid == 0) atomicAdd(&g_acc[0], (double)sred);
}

// ---------------------------------------------------------------------------
__global__ void final_kernel(float* __restrict__ out) {
    double pos = g_acc[1] / (double)g_numvalid;
    double neg = (g_acc[0] - g_acc[2]) / (double)NCLS;
    out[0] = (float)(pos + neg);
}

// ---------------------------------------------------------------------------
extern "C" void kernel_launch(void* const* d_in, const int* in_sizes, int n_in,
                              void* d_out, int out_size) {
    const float* X    = (const float*)d_in[0];
    const int*   T    = (const int*)d_in[1];
    const float* Ptan = (const float*)d_in[2];
    float* out = (float*)d_out;

    prep_kernel<<<NCLS + NROW, 128>>>(Ptan, X);
    scatter_kernel<<<(NROW + 255) / 256, 256>>>(T);
    count_kernel<<<1, 1024>>>();
    pos_kernel<<<64, 256>>>(X, T);
    dim3 grid(NCLS / 128, NROW / 128);
    fused_kernel<<<grid, 256>>>();
    final_kernel<<<1, 1>>>(out);
}

// round 17
// speedup vs baseline: 1.2756x; 1.2756x over previous
#include <cuda_runtime.h>
#include <cuda_bf16.h>
#include <cstdint>
#include <cmath>

// Problem constants (fixed by reference)
#define NROW 8192       // N
#define NCLS 8192       // NB_CLASSES
#define DIM  128        // SZ_EMBED

__device__ __forceinline__ float flog2(float x){ float y; asm("lg2.approx.f32 %0, %1;" : "=f"(y) : "f"(x)); return y; }
__device__ __forceinline__ float fexp2(float x){ float y; asm("ex2.approx.f32 %0, %1;" : "=f"(y) : "f"(x)); return y; }
__device__ __forceinline__ float frcp (float x){ float y; asm("rcp.approx.f32 %0, %1;" : "=f"(y) : "f"(x)); return y; }
__device__ __forceinline__ float fsqrt(float x){ float y; asm("sqrt.approx.f32 %0, %1;" : "=f"(y) : "f"(x)); return y; }
__device__ __forceinline__ uint32_t f2tf32(float x){ uint32_t y; asm("cvt.rna.tf32.f32 %0, %1;" : "=r"(y) : "f"(x)); return y; }

#define CP_ASYNC16(dst32, srcp) \
    asm volatile("cp.async.cg.shared.global [%0], [%1], 16;" :: "r"(dst32), "l"(srcp))
#define CP_COMMIT()  asm volatile("cp.async.commit_group;")
#define CP_WAIT0()   asm volatile("cp.async.wait_group 0;")

__constant__ float c_C        = 0.1f;
__constant__ float c_SQRTC    = 0.31622776601683794f;
__constant__ float c_INVSQRTC = 3.1622776601683795f;   // 1/sqrt(c) = sqrt(10)

// Scratch (static device allocations are allowed)
__device__ float  g_P [NCLS * DIM];  // projected proxies (tf32-rounded)
__device__ float  g_Xt[NROW * DIM];  // X, tf32-rounded
__device__ float  g_y2[NCLS];        // ||P_j||^2
__device__ float  g_x2[NROW];        // ||X_i||^2
__device__ double g_acc[3];          // 0: neg_sum, 1: pos_sum, 2: neg_corr
__device__ int    g_flags[NCLS];
__device__ int    g_numvalid;

// ---------------------------------------------------------------------------
// prep: bid < NCLS -> project proxy row; else -> x2 + tf32 copy of X row.
__global__ void prep_kernel(const float* __restrict__ Ptan,
                            const float* __restrict__ X) {
    int bid = blockIdx.x;
    int t = threadIdx.x;
    __shared__ float ws[4];

    if (bid < NCLS) {
        int row = bid;
        float p = Ptan[row * DIM + t];
        float s = p * p;
        #pragma unroll
        for (int off = 16; off > 0; off >>= 1) s += __shfl_xor_sync(0xffffffffu, s, off);
        if ((t & 31) == 0) ws[t >> 5] = s;
        __syncthreads();
        float sum = ws[0] + ws[1] + ws[2] + ws[3];

        float nrm = fmaxf(sqrtf(sum), 1e-15f);
        float sc1 = fminf(1.0f, 2.3f / nrm);        // feature clipping
        p *= sc1;
        float un = fmaxf(nrm * sc1, 1e-15f);
        float a  = c_SQRTC * un;
        float th = tanhf(a);
        float g  = th * p / a;                       // expmap0
        float gn = fmaxf(th * c_INVSQRTC, 1e-15f);   // ||g|| = tanh(a)/sqrt(c)
        const float maxnorm = (1.0f - 1e-3f) * 3.1622776601683795f;
        float sc2 = (gn > maxnorm) ? (maxnorm / gn) : 1.0f;
        g *= sc2;
        g_P[row * DIM + t] = __uint_as_float(f2tf32(g));
        if (t == 0) {
            float gf = fminf(gn, maxnorm);
            g_y2[row] = gf * gf;
        }
    } else {
        int row = bid - NCLS;
        float v = X[row * DIM + t];
        g_Xt[row * DIM + t] = __uint_as_float(f2tf32(v));
        float s = v * v;
        #pragma unroll
        for (int off = 16; off > 0; off >>= 1) s += __shfl_xor_sync(0xffffffffu, s, off);
        if ((t & 31) == 0) ws[t >> 5] = s;
        __syncthreads();
        if (t == 0) g_x2[row] = ws[0] + ws[1] + ws[2] + ws[3];
    }
}

// ---------------------------------------------------------------------------
// scatter flags + zero accumulators (flags were cleared by count_kernel of the
// previous replay; __device__ globals are zero-initialized on first load).
__global__ void scatter_kernel(const int* __restrict__ T) {
    int i = blockIdx.x * blockDim.x + threadIdx.x;
    if (i < NROW) g_flags[T[i]] = 1;
    if (blockIdx.x == 0 && threadIdx.x < 3) g_acc[threadIdx.x] = 0.0;
}

// count valid classes, then self-clear flags for the next graph replay.
__global__ void count_kernel() {
    int t = threadIdx.x;
    int s = 0;
    for (int i = t; i < NCLS; i += 1024) { s += g_flags[i]; g_flags[i] = 0; }
    #pragma unroll
    for (int off = 16; off > 0; off >>= 1) s += __shfl_xor_sync(0xffffffffu, s, off);
    __shared__ int ws[32];
    if ((t & 31) == 0) ws[t >> 5] = s;
    __syncthreads();
    if (t < 32) {
        int v = ws[t];
        #pragma unroll
        for (int off = 16; off > 0; off >>= 1) v += __shfl_xor_sync(0xffffffffu, v, off);
        if (t == 0) g_numvalid = v;
    }
}

// ---------------------------------------------------------------------------
// Positive pairs: 128 blocks x 256, each warp handles 8 pairs serially
// (halved critical path vs 16; block size/atomic structure unchanged).
__global__ void pos_kernel(const float* __restrict__ X, const int* __restrict__ T) {
    const int wid  = threadIdx.x >> 5;
    const int lane = threadIdx.x & 31;
    const int base = blockIdx.x * 64 + wid * 8;

    float poss = 0.0f, negc = 0.0f;
    for (int k = 0; k < 8; k++) {
        const int i = base + k;
        const int j = __ldg(&T[i]);
        const float* xr = &X  [i * DIM];
        const float* pr = &g_P[j * DIM];
        float dot = 0.0f;
        #pragma unroll
        for (int u = 0; u < 4; u++)
            dot = fmaf(xr[lane + u * 32], pr[lane + u * 32], dot);
        #pragma unroll
        for (int off = 16; off > 0; off >>= 1)
            dot += __shfl_xor_sync(0xffffffffu, dot, off);
        if (lane == 0) {
            const float C  = 0.1f;
            const float x2 = g_x2[i];
            const float y2 = g_y2[j];
            float t2 = fmaxf(x2 - 2.0f * dot + y2, 0.0f);     // ||x-y||^2
            float u  = 2.0f * C * t2 / ((1.0f - C * x2) * (1.0f - C * y2));
            float w  = 1.0f + u + sqrtf(u * (u + 2.0f));
            float d  = 3.1622776601683795f * logf(w);          // (1/sqrt(c))*arcosh(1+u)
            float sn = log1pf(expf(-d));                       // softplus(-d)
            poss += d + sn;                                    // softplus(d)
            negc += sn;
        }
    }
    if (lane == 0) {
        atomicAdd(&g_acc[1], (double)poss);
        atomicAdd(&g_acc[2], (double)negc);
    }
}

// ---------------------------------------------------------------------------
// Fused tf32 tensor-core GEMM (xy = X @ P^T) + Poincare distance + softplus(-d)
// over ALL pairs (positives corrected by pos_kernel).
// BM=BN=128, BK=16. 256 threads = 8 warps (4 in M x 2 in N), warp tile 32x64.
// Round-11 proven layout (SSTR=20, LDS.32 fragments); single sync per K-tile
// (top-of-loop CP_WAIT0 + syncthreads covers both hazards).
#define SSTR 20

__device__ __forceinline__ void mma_tf32_v(float* d, uint32_t a0, uint32_t a1,
                                           uint32_t a2, uint32_t a3,
                                           uint32_t b0, uint32_t b1) {
    asm volatile(
        "mma.sync.aligned.m16n8k8.row.col.f32.tf32.tf32.f32 "
        "{%0,%1,%2,%3}, {%4,%5,%6,%7}, {%8,%9}, {%0,%1,%2,%3};"
        : "+f"(d[0]), "+f"(d[1]), "+f"(d[2]), "+f"(d[3])
        : "r"(a0), "r"(a1), "r"(a2), "r"(a3), "r"(b0), "r"(b1));
}

__global__ __launch_bounds__(256, 2)
void fused_kernel() {
    __shared__ __align__(16) float Xs[2][128][SSTR];
    __shared__ __align__(16) float Ps[2][128][SSTR];
    __shared__ float sred;

    const int tid  = threadIdx.x;
    const int wid  = tid >> 5;
    const int lane = tid & 31;
    const int wm   = wid & 3;        // warp row 0..3 (M)
    const int wn   = wid >> 2;       // warp col 0..1 (N)
    const int g    = lane >> 2;      // group id 0..7
    const int t4   = lane & 3;       // thread in group 0..3
    const int rowBase = blockIdx.y * 128;
    const int colBase = blockIdx.x * 128;

    // staging map: each thread copies 2 x 16B of X and 2 x 16B of P per tile
    const int lrow = tid >> 1;          // 0..127
    const int lc0  = (tid & 1) * 2;     // float4 index base {0,2}
    const float* xg = &g_Xt[(rowBase + lrow) * DIM];
    const float* pg = &g_P [(colBase + lrow) * DIM];

    uint32_t xs_dst[2], ps_dst[2];
    #pragma unroll
    for (int u = 0; u < 2; u++) {
        xs_dst[u] = (uint32_t)__cvta_generic_to_shared(&Xs[0][lrow][(lc0 + u) * 4]);
        ps_dst[u] = (uint32_t)__cvta_generic_to_shared(&Ps[0][lrow][(lc0 + u) * 4]);
    }
    const uint32_t bufStride = (uint32_t)((char*)&Xs[1][0][0] - (char*)&Xs[0][0][0]);

    float acc[2][8][4];
    #pragma unroll
    for (int mt = 0; mt < 2; mt++)
        #pragma unroll
        for (int nt = 0; nt < 8; nt++)
            #pragma unroll
            for (int c = 0; c < 4; c++) acc[mt][nt][c] = 0.0f;

    // prefetch tile 0 into buffer 0
    #pragma unroll
    for (int u = 0; u < 2; u++) {
        CP_ASYNC16(xs_dst[u], xg + (lc0 + u) * 4);
        CP_ASYNC16(ps_dst[u], pg + (lc0 + u) * 4);
    }
    CP_COMMIT();

    const int rA = wm * 32;     // warp M offset in tile
    const int nB = wn * 64;     // warp N offset in tile

    int buf = 0;
    #pragma unroll
    for (int tt = 0; tt < DIM / 16; tt++) {
        // Drain our copies, then barrier: publishes the new tile to all
        // threads AND guarantees everyone finished reading the old buffer
        // (program order) before we overwrite it below.
        CP_WAIT0();
        __syncthreads();
        // prefetch next tile into the other buffer (overlaps compute below)
        if (tt < DIM / 16 - 1) {
            const int kn = (tt + 1) * 16;
            const uint32_t off = (buf ^ 1) ? bufStride : 0u;
            #pragma unroll
            for (int u = 0; u < 2; u++) {
                CP_ASYNC16(xs_dst[u] + off, xg + kn + (lc0 + u) * 4);
                CP_ASYNC16(ps_dst[u] + off, pg + kn + (lc0 + u) * 4);
            }
            CP_COMMIT();
        }
        // compute current tile: 2 k8 steps
        #pragma unroll
        for (int ks = 0; ks < 2; ks++) {
            const int k8 = ks * 8;
            uint32_t bf[8][2];
            #pragma unroll
            for (int nt = 0; nt < 8; nt++) {
                const float* bp = &Ps[buf][nB + nt * 8 + g][k8 + t4];
                bf[nt][0] = __float_as_uint(bp[0]);
                bf[nt][1] = __float_as_uint(bp[4]);
            }
            #pragma unroll
            for (int mt = 0; mt < 2; mt++) {
                const float* ap0 = &Xs[buf][rA + mt * 16 + g][k8 + t4];
                const float* ap1 = &Xs[buf][rA + mt * 16 + g + 8][k8 + t4];
                const uint32_t a0 = __float_as_uint(ap0[0]);
                const uint32_t a1 = __float_as_uint(ap1[0]);
                const uint32_t a2 = __float_as_uint(ap0[4]);
                const uint32_t a3 = __float_as_uint(ap1[4]);
                #pragma unroll
                for (int nt = 0; nt < 8; nt++)
                    mma_tf32_v(acc[mt][nt], a0, a1, a2, a3, bf[nt][0], bf[nt][1]);
            }
        }
        buf ^= 1;
    }

    // ---------------- Epilogue (negatives only, arcosh form) ----------------
    // element (mt, nt, c): row h = mt*2 + (c>>1), col q = nt*2 + (c&1)
    const int rowW = rowBase + rA;
    const int colW = colBase + nB;
    const float C = c_C;

    float x2r[4], bx2c[4];
    #pragma unroll
    for (int h = 0; h < 4; h++) {
        int r = rowW + (h >> 1) * 16 + (h & 1) * 8 + g;
        float x2 = __ldg(&g_x2[r]);
        x2r[h]  = x2;
        bx2c[h] = 2.0f * C * frcp(1.0f - C * x2);    // 2c/(1-c*x2)
    }
    float y2c[16], byc[16];
    #pragma unroll
    for (int q = 0; q < 16; q++) {
        int cc = colW + (q >> 1) * 8 + 2 * t4 + (q & 1);
        float y2 = __ldg(&g_y2[cc]);
        y2c[q] = y2;
        byc[q] = frcp(1.0f - C * y2);                // 1/(1-c*y2)
    }

    const float KNEG = -3.1622776601683795f;         // -1/sqrt(c)
    float negs = 0.0f;

    #pragma unroll
    for (int mt = 0; mt < 2; mt++) {
        #pragma unroll
        for (int nt = 0; nt < 8; nt++) {
            #pragma unroll
            for (int c = 0; c < 4; c++) {
                const int h = mt * 2 + (c >> 1);
                const int q = nt * 2 + (c & 1);
                const float xy = acc[mt][nt][c];
                float t = fmaf(-2.0f, xy, x2r[h]);   // ||x-y||^2 = x2 - 2xy + y2
                t += y2c[q];
                t = fmaxf(t, 0.0f);
                float u = t * bx2c[h] * byc[q];      // 2c||x-y||^2/((1-cx2)(1-cy2))
                float v = u + 2.0f;
                float s = fsqrt(u * v);              // sqrt(u^2+2u)
                float w = (1.0f + u) + s;            // arcosh(1+u) = ln(w)
                float L = flog2(w);
                float e = fexp2(KNEG * L);           // exp(-d), d = ln(w)/sqrt(c)
                negs = fmaf(0.6931471805599453f, flog2(1.0f + e), negs);  // +softplus(-d)
            }
        }
    }

    // block reduction -> double atomic
    #pragma unroll
    for (int off = 16; off > 0; off >>= 1)
        negs += __shfl_xor_sync(0xffffffffu, negs, off);
    if (tid == 0) sred = 0.0f;
    __syncthreads();
    if (lane == 0) atomicAdd(&sred, negs);
    __syncthreads();
    if (tid == 0) atomicAdd(&g_acc[0], (double)sred);
}

// ---------------------------------------------------------------------------
__global__ void final_kernel(float* __restrict__ out) {
    double pos = g_acc[1] / (double)g_numvalid;
    double neg = (g_acc[0] - g_acc[2]) / (double)NCLS;
    out[0] = (float)(pos + neg);
}

// ---------------------------------------------------------------------------
extern "C" void kernel_launch(void* const* d_in, const int* in_sizes, int n_in,
                              void* d_out, int out_size) {
    const float* X    = (const float*)d_in[0];
    const int*   T    = (const int*)d_in[1];
    const float* Ptan = (const float*)d_in[2];
    float* out = (float*)d_out;

    prep_kernel<<<NCLS + NROW, 128>>>(Ptan, X);
    scatter_kernel<<<(NROW + 255) / 256, 256>>>(T);
    count_kernel<<<1, 1024>>>();
    pos_kernel<<<128, 256>>>(X, T);
    dim3 grid(NCLS / 128, NROW / 128);
    fused_kernel<<<grid, 256>>>();
    final_kernel<<<1, 1>>>(out);
}